// round 1
// baseline (speedup 1.0000x reference)
#include <cuda_runtime.h>
#include <math.h>

#define D_MODEL 768
#define NH      12
#define DH      64
#define SEQ     512
#define BATCH   8
#define ROWS    (BATCH*SEQ)   /* 4096 */
#define DFF     3072
#define NLAYERS 12
#define LN1E4   9.210340371976184f

// ----------------------------------------------------------------------------
// Scratch (device globals; no allocation anywhere)
// ----------------------------------------------------------------------------
__device__ float g_x  [ROWS*D_MODEL];
__device__ float g_hn [ROWS*D_MODEL];
__device__ float g_qt [ROWS*D_MODEL];   // pre-rope Q, later reused as attn-out (B,L,D)
__device__ float g_kt [ROWS*D_MODEL];
__device__ float g_vt [ROWS*D_MODEL];
__device__ float g_q  [ROWS*D_MODEL];   // post-rope (B,H,L,DH)
__device__ float g_k  [ROWS*D_MODEL];
__device__ float g_sc [(size_t)BATCH*NH*SEQ*SEQ];   // 100.7 MB scores/probs
__device__ float g_gate[ROWS*DFF];      // also reused as box_sin features at embed
__device__ float g_hid [ROWS*DFF];

// ----------------------------------------------------------------------------
// Generic SGEMM: C[M,N] = A[M,K] @ B[K,N] (+C if ACC) (+bias if BIAS)
// Requires K % 16 == 0, M % 64 == 0. N arbitrary (guarded).
// 256 threads, BM=BN=64, BK=16, 4x4 micro-tile.
// ----------------------------------------------------------------------------
template<bool ACC, bool BIAS>
__global__ void gemm_kernel(const float* __restrict__ A, const float* __restrict__ B,
                            const float* __restrict__ bias, float* __restrict__ C,
                            int M, int N, int K)
{
    __shared__ float As[16][65];
    __shared__ float Bs[16][64];
    const int tid = threadIdx.x;
    const int tx = tid & 15, ty = tid >> 4;
    const int m0 = blockIdx.y * 64, n0 = blockIdx.x * 64;

    const int arow = tid >> 2;            // 0..63
    const int akk  = (tid & 3) * 4;       // 0,4,8,12
    const int bkk  = ty;                  // 0..15
    const int bcol = tx * 4;              // 0..60

    float acc[4][4];
    #pragma unroll
    for (int i = 0; i < 4; i++)
        #pragma unroll
        for (int j = 0; j < 4; j++) acc[i][j] = 0.f;

    for (int k0 = 0; k0 < K; k0 += 16) {
        // A tile (always in-bounds: M%64==0, K%16==0)
        float4 av = *(const float4*)(A + (size_t)(m0 + arow) * K + k0 + akk);
        As[akk+0][arow] = av.x; As[akk+1][arow] = av.y;
        As[akk+2][arow] = av.z; As[akk+3][arow] = av.w;
        // B tile (N guarded)
        {
            int gn = n0 + bcol;
            const float* Bp = B + (size_t)(k0 + bkk) * N + gn;
            float4 bv;
            if (gn + 3 < N) {
                bv = *(const float4*)Bp;
            } else {
                bv.x = (gn+0 < N) ? Bp[0] : 0.f;
                bv.y = (gn+1 < N) ? Bp[1] : 0.f;
                bv.z = (gn+2 < N) ? Bp[2] : 0.f;
                bv.w = (gn+3 < N) ? Bp[3] : 0.f;
            }
            *(float4*)&Bs[bkk][bcol] = bv;
        }
        __syncthreads();
        #pragma unroll
        for (int kk = 0; kk < 16; kk++) {
            float a0 = As[kk][ty*4+0], a1 = As[kk][ty*4+1];
            float a2 = As[kk][ty*4+2], a3 = As[kk][ty*4+3];
            float4 bv = *(const float4*)&Bs[kk][tx*4];
            acc[0][0] += a0*bv.x; acc[0][1] += a0*bv.y; acc[0][2] += a0*bv.z; acc[0][3] += a0*bv.w;
            acc[1][0] += a1*bv.x; acc[1][1] += a1*bv.y; acc[1][2] += a1*bv.z; acc[1][3] += a1*bv.w;
            acc[2][0] += a2*bv.x; acc[2][1] += a2*bv.y; acc[2][2] += a2*bv.z; acc[2][3] += a2*bv.w;
            acc[3][0] += a3*bv.x; acc[3][1] += a3*bv.y; acc[3][2] += a3*bv.z; acc[3][3] += a3*bv.w;
        }
        __syncthreads();
    }

    #pragma unroll
    for (int i = 0; i < 4; i++) {
        int gm = m0 + ty*4 + i;
        #pragma unroll
        for (int j = 0; j < 4; j++) {
            int gn = n0 + tx*4 + j;
            if (gn < N) {
                float v = acc[i][j];
                if (BIAS) v += bias[gn];
                size_t off = (size_t)gm * N + gn;
                if (ACC) v += C[off];
                C[off] = v;
            }
        }
    }
}

// ----------------------------------------------------------------------------
// box Fourier features: bs[row, i*192 + 2j] = cos(box[row,i]*theta_j), +1 = sin
// theta_j = 10000^(-2j/192), j in [0,96)
// ----------------------------------------------------------------------------
__global__ void boxsin_kernel(const float* __restrict__ box, float* __restrict__ bs)
{
    int idx = blockIdx.x * blockDim.x + threadIdx.x;     // ROWS*4*96
    if (idx >= ROWS*4*96) return;
    int j   = idx % 96;
    int i   = (idx / 96) & 3;
    int row = idx / 384;
    float theta = expf(-(float)j * (LN1E4 / 96.f));
    float ang = box[row*4 + i] * theta;
    float s, c;
    sincosf(ang, &s, &c);
    bs[(size_t)row*D_MODEL + i*192 + 2*j    ] = c;
    bs[(size_t)row*D_MODEL + i*192 + 2*j + 1] = s;
}

// ----------------------------------------------------------------------------
// RMSNorm: out = x * rsqrt(mean(x^2)+eps) * w   (row-wise over 768)
// ----------------------------------------------------------------------------
__global__ void rmsnorm_kernel(const float* __restrict__ x, const float* __restrict__ w,
                               float* __restrict__ out)
{
    __shared__ float red[256];
    int row = blockIdx.x;
    const float* xr = x + (size_t)row * D_MODEL;
    float s = 0.f;
    for (int i = threadIdx.x; i < D_MODEL; i += 256) { float v = xr[i]; s += v*v; }
    red[threadIdx.x] = s; __syncthreads();
    for (int off = 128; off > 0; off >>= 1) {
        if (threadIdx.x < off) red[threadIdx.x] += red[threadIdx.x + off];
        __syncthreads();
    }
    float inv = rsqrtf(red[0] / (float)D_MODEL + 1e-6f);
    float* orow = out + (size_t)row * D_MODEL;
    for (int i = threadIdx.x; i < D_MODEL; i += 256) orow[i] = xr[i] * inv * w[i];
}

// ----------------------------------------------------------------------------
// RoPE + transpose to (B,H,L,DH) for q and k.
// idx -> (b, l, h, j), j in [0,32)
// ----------------------------------------------------------------------------
__global__ void rope_kernel(const float* __restrict__ qt, const float* __restrict__ kt,
                            float* __restrict__ qo, float* __restrict__ ko)
{
    int idx = blockIdx.x * blockDim.x + threadIdx.x;   // BATCH*SEQ*NH*32
    if (idx >= BATCH*SEQ*NH*32) return;
    int j = idx & 31;
    int h = (idx >> 5) % NH;
    int l = (idx >> 5) / NH % SEQ;
    int b = idx / (32 * NH * SEQ);
    float theta = expf(-(float)j * (LN1E4 / 32.f));
    float ang = (float)l * theta;
    float s, c;
    sincosf(ang, &s, &c);
    size_t in  = ((size_t)(b*SEQ + l)) * D_MODEL + h*DH + 2*j;
    size_t out = ((size_t)((b*NH + h)*SEQ + l)) * DH + 2*j;
    float qr = qt[in], qi = qt[in+1];
    qo[out]   = qr*c - qi*s;
    qo[out+1] = qr*s + qi*c;
    float kr = kt[in], ki = kt[in+1];
    ko[out]   = kr*c - ki*s;
    ko[out+1] = kr*s + ki*c;
}

// ----------------------------------------------------------------------------
// Scores: S[bh, m, n] = (Q[bh,m,:] . K[bh,n,:]) / 8   — skip strictly-upper tiles
// ----------------------------------------------------------------------------
__global__ void attn_scores_kernel(const float* __restrict__ Q, const float* __restrict__ Kd,
                                   float* __restrict__ S)
{
    int bh = blockIdx.z;
    int m0 = blockIdx.y * 64, n0 = blockIdx.x * 64;
    if (n0 > m0 + 63) return;   // never read (causal)
    const float* Qb = Q  + (size_t)bh * SEQ * DH;
    const float* Kb = Kd + (size_t)bh * SEQ * DH;
    float* Sb = S + (size_t)bh * SEQ * SEQ;

    __shared__ float Qs[16][65];
    __shared__ float Ks[16][65];
    const int tid = threadIdx.x;
    const int tx = tid & 15, ty = tid >> 4;
    const int row = tid >> 2, kk4 = (tid & 3) * 4;

    float acc[4][4];
    #pragma unroll
    for (int i = 0; i < 4; i++)
        #pragma unroll
        for (int j = 0; j < 4; j++) acc[i][j] = 0.f;

    for (int k0 = 0; k0 < DH; k0 += 16) {
        float4 qv = *(const float4*)(Qb + (size_t)(m0 + row) * DH + k0 + kk4);
        Qs[kk4+0][row] = qv.x; Qs[kk4+1][row] = qv.y;
        Qs[kk4+2][row] = qv.z; Qs[kk4+3][row] = qv.w;
        float4 kv = *(const float4*)(Kb + (size_t)(n0 + row) * DH + k0 + kk4);
        Ks[kk4+0][row] = kv.x; Ks[kk4+1][row] = kv.y;
        Ks[kk4+2][row] = kv.z; Ks[kk4+3][row] = kv.w;
        __syncthreads();
        #pragma unroll
        for (int kk = 0; kk < 16; kk++) {
            float a0 = Qs[kk][ty*4+0], a1 = Qs[kk][ty*4+1];
            float a2 = Qs[kk][ty*4+2], a3 = Qs[kk][ty*4+3];
            float b0 = Ks[kk][tx*4+0], b1 = Ks[kk][tx*4+1];
            float b2 = Ks[kk][tx*4+2], b3 = Ks[kk][tx*4+3];
            acc[0][0] += a0*b0; acc[0][1] += a0*b1; acc[0][2] += a0*b2; acc[0][3] += a0*b3;
            acc[1][0] += a1*b0; acc[1][1] += a1*b1; acc[1][2] += a1*b2; acc[1][3] += a1*b3;
            acc[2][0] += a2*b0; acc[2][1] += a2*b1; acc[2][2] += a2*b2; acc[2][3] += a2*b3;
            acc[3][0] += a3*b0; acc[3][1] += a3*b1; acc[3][2] += a3*b2; acc[3][3] += a3*b3;
        }
        __syncthreads();
    }
    const float inv = 0.125f;   // 1/sqrt(64)
    #pragma unroll
    for (int i = 0; i < 4; i++)
        #pragma unroll
        for (int j = 0; j < 4; j++)
            Sb[(size_t)(m0 + ty*4 + i) * SEQ + n0 + tx*4 + j] = acc[i][j] * inv;
}

// ----------------------------------------------------------------------------
// Causal row softmax over m<=l; writes zeros for m>l.  One block per (bh,l) row.
// ----------------------------------------------------------------------------
__global__ void softmax_kernel(float* __restrict__ S)
{
    __shared__ float red[128];
    int row = blockIdx.x;          // bh*SEQ + l
    int l = row & (SEQ - 1);
    float* Sr = S + (size_t)row * SEQ;
    int t = threadIdx.x;

    float mx = -1e30f;
    for (int i = t; i <= l; i += 128) mx = fmaxf(mx, Sr[i]);
    red[t] = mx; __syncthreads();
    for (int off = 64; off > 0; off >>= 1) {
        if (t < off) red[t] = fmaxf(red[t], red[t + off]);
        __syncthreads();
    }
    mx = red[0]; __syncthreads();

    float e[4];
    float sum = 0.f;
    #pragma unroll
    for (int j = 0; j < 4; j++) {
        int i = t + j * 128;
        e[j] = (i <= l) ? expf(Sr[i] - mx) : 0.f;
        sum += e[j];
    }
    red[t] = sum; __syncthreads();
    for (int off = 64; off > 0; off >>= 1) {
        if (t < off) red[t] += red[t + off];
        __syncthreads();
    }
    float invs = 1.f / red[0];
    #pragma unroll
    for (int j = 0; j < 4; j++) {
        int i = t + j * 128;
        Sr[i] = e[j] * invs;
    }
}

// ----------------------------------------------------------------------------
// AV: O[b,l, h*64+d] = sum_m P[bh,l,m] * V[(b,m), h*64+d]; causal k-range.
// ----------------------------------------------------------------------------
__global__ void attn_av_kernel(const float* __restrict__ P, const float* __restrict__ V,
                               float* __restrict__ O)
{
    int bh = blockIdx.y;
    int m0 = blockIdx.x * 64;
    int b = bh / NH, h = bh % NH;
    const float* Pb = P + (size_t)bh * SEQ * SEQ;

    __shared__ float Ps[16][65];
    __shared__ float Vs[16][64];
    const int tid = threadIdx.x;
    const int tx = tid & 15, ty = tid >> 4;
    const int prow = tid >> 2, pkk = (tid & 3) * 4;

    float acc[4][4];
    #pragma unroll
    for (int i = 0; i < 4; i++)
        #pragma unroll
        for (int j = 0; j < 4; j++) acc[i][j] = 0.f;

    int kend = m0 + 64;   // P[l,m]=0 for m>l
    for (int k0 = 0; k0 < kend; k0 += 16) {
        float4 pv = *(const float4*)(Pb + (size_t)(m0 + prow) * SEQ + k0 + pkk);
        Ps[pkk+0][prow] = pv.x; Ps[pkk+1][prow] = pv.y;
        Ps[pkk+2][prow] = pv.z; Ps[pkk+3][prow] = pv.w;
        float4 vv = *(const float4*)(V + ((size_t)(b*SEQ + k0 + ty)) * D_MODEL + h*DH + tx*4);
        *(float4*)&Vs[ty][tx*4] = vv;
        __syncthreads();
        #pragma unroll
        for (int kk = 0; kk < 16; kk++) {
            float a0 = Ps[kk][ty*4+0], a1 = Ps[kk][ty*4+1];
            float a2 = Ps[kk][ty*4+2], a3 = Ps[kk][ty*4+3];
            float4 bv = *(const float4*)&Vs[kk][tx*4];
            acc[0][0] += a0*bv.x; acc[0][1] += a0*bv.y; acc[0][2] += a0*bv.z; acc[0][3] += a0*bv.w;
            acc[1][0] += a1*bv.x; acc[1][1] += a1*bv.y; acc[1][2] += a1*bv.z; acc[1][3] += a1*bv.w;
            acc[2][0] += a2*bv.x; acc[2][1] += a2*bv.y; acc[2][2] += a2*bv.z; acc[2][3] += a2*bv.w;
            acc[3][0] += a3*bv.x; acc[3][1] += a3*bv.y; acc[3][2] += a3*bv.z; acc[3][3] += a3*bv.w;
        }
        __syncthreads();
    }
    #pragma unroll
    for (int i = 0; i < 4; i++)
        #pragma unroll
        for (int j = 0; j < 4; j++)
            O[((size_t)(b*SEQ + m0 + ty*4 + i)) * D_MODEL + h*DH + tx*4 + j] = acc[i][j];
}

// ----------------------------------------------------------------------------
// SiLU-mul: g = silu(g) * h
// ----------------------------------------------------------------------------
__global__ void silu_mul_kernel(float* __restrict__ g, const float* __restrict__ h, int n)
{
    for (int i = blockIdx.x * blockDim.x + threadIdx.x; i < n; i += gridDim.x * blockDim.x) {
        float x = g[i];
        g[i] = (x / (1.f + expf(-x))) * h[i];
    }
}

// ----------------------------------------------------------------------------
// Launch
// ----------------------------------------------------------------------------
extern "C" void kernel_launch(void* const* d_in, const int* in_sizes, int n_in,
                              void* d_out, int out_size)
{
    const float* patch        = (const float*)d_in[0];
    const float* box          = (const float*)d_in[1];
    const float* patch_W      = (const float*)d_in[2];
    const float* patch_b      = (const float*)d_in[3];
    const float* box_W        = (const float*)d_in[4];
    const float* box_b        = (const float*)d_in[5];
    const float* Wq           = (const float*)d_in[6];
    const float* Wk           = (const float*)d_in[7];
    const float* Wv           = (const float*)d_in[8];
    const float* Wo           = (const float*)d_in[9];
    const float* attn_norm_w  = (const float*)d_in[10];
    const float* gate_W       = (const float*)d_in[11];
    const float* hidden_W     = (const float*)d_in[12];
    const float* ffn_out_W    = (const float*)d_in[13];
    const float* ffn_norm_w   = (const float*)d_in[14];
    const float* reward_norm_w= (const float*)d_in[15];
    const float* reward_W     = (const float*)d_in[16];
    const float* reward_b     = (const float*)d_in[17];
    const float* label_norm_w = (const float*)d_in[18];
    const float* label_W      = (const float*)d_in[19];
    const float* label_b      = (const float*)d_in[20];
    const float* box_norm_w   = (const float*)d_in[21];
    const float* boxh_W       = (const float*)d_in[22];
    const float* boxh_b       = (const float*)d_in[23];
    float* out = (float*)d_out;

    float *x, *hn, *qt, *kt, *vt, *q, *k, *sc, *gate, *hid;
    { void* p;
      cudaGetSymbolAddress(&p, g_x);    x    = (float*)p;
      cudaGetSymbolAddress(&p, g_hn);   hn   = (float*)p;
      cudaGetSymbolAddress(&p, g_qt);   qt   = (float*)p;
      cudaGetSymbolAddress(&p, g_kt);   kt   = (float*)p;
      cudaGetSymbolAddress(&p, g_vt);   vt   = (float*)p;
      cudaGetSymbolAddress(&p, g_q);    q    = (float*)p;
      cudaGetSymbolAddress(&p, g_k);    k    = (float*)p;
      cudaGetSymbolAddress(&p, g_sc);   sc   = (float*)p;
      cudaGetSymbolAddress(&p, g_gate); gate = (float*)p;
      cudaGetSymbolAddress(&p, g_hid);  hid  = (float*)p;
    }

    const dim3 g768 (D_MODEL/64, ROWS/64);   // N=768 GEMMs
    const dim3 g3072(DFF/64,     ROWS/64);   // N=3072 GEMMs

    // ---- Embedding ----
    {
        int n = ROWS * 4 * 96;
        boxsin_kernel<<<(n + 255) / 256, 256>>>(box, gate);   // gate reused as box_sin
    }
    gemm_kernel<false, true><<<g768, 256>>>(patch, patch_W, patch_b, x, ROWS, D_MODEL, D_MODEL);
    gemm_kernel<true,  true><<<g768, 256>>>(gate,  box_W,   box_b,   x, ROWS, D_MODEL, D_MODEL);

    // ---- Layers ----
    for (int L = 0; L < NLAYERS; L++) {
        const float* wq  = Wq + (size_t)L * D_MODEL * D_MODEL;
        const float* wk  = Wk + (size_t)L * D_MODEL * D_MODEL;
        const float* wv  = Wv + (size_t)L * D_MODEL * D_MODEL;
        const float* wo  = Wo + (size_t)L * D_MODEL * D_MODEL;
        const float* anw = attn_norm_w + (size_t)L * D_MODEL;
        const float* gw  = gate_W   + (size_t)L * D_MODEL * DFF;
        const float* hw  = hidden_W + (size_t)L * D_MODEL * DFF;
        const float* ow  = ffn_out_W+ (size_t)L * DFF * D_MODEL;
        const float* fnw = ffn_norm_w + (size_t)L * D_MODEL;

        // attention
        rmsnorm_kernel<<<ROWS, 256>>>(x, anw, hn);
        gemm_kernel<false, false><<<g768, 256>>>(hn, wq, nullptr, qt, ROWS, D_MODEL, D_MODEL);
        gemm_kernel<false, false><<<g768, 256>>>(hn, wk, nullptr, kt, ROWS, D_MODEL, D_MODEL);
        gemm_kernel<false, false><<<g768, 256>>>(hn, wv, nullptr, vt, ROWS, D_MODEL, D_MODEL);
        {
            int n = BATCH * SEQ * NH * 32;
            rope_kernel<<<(n + 255) / 256, 256>>>(qt, kt, q, k);
        }
        attn_scores_kernel<<<dim3(SEQ/64, SEQ/64, BATCH*NH), 256>>>(q, k, sc);
        softmax_kernel<<<BATCH*NH*SEQ, 128>>>(sc);
        attn_av_kernel<<<dim3(SEQ/64, BATCH*NH), 256>>>(sc, vt, qt);   // qt reused as O
        gemm_kernel<true, false><<<g768, 256>>>(qt, wo, nullptr, x, ROWS, D_MODEL, D_MODEL);

        // FFN
        rmsnorm_kernel<<<ROWS, 256>>>(x, fnw, hn);
        gemm_kernel<false, false><<<g3072, 256>>>(hn, gw, nullptr, gate, ROWS, DFF, D_MODEL);
        gemm_kernel<false, false><<<g3072, 256>>>(hn, hw, nullptr, hid,  ROWS, DFF, D_MODEL);
        silu_mul_kernel<<<2048, 256>>>(gate, hid, ROWS * DFF);
        gemm_kernel<true, false><<<g768, 256>>>(gate, ow, nullptr, x, ROWS, D_MODEL, DFF);
    }

    // ---- Heads ----
    // output layout: reward (B,L,2) | label (B,L,1000) | box (B,L,4)
    float* out_reward = out;
    float* out_label  = out + (size_t)ROWS * 2;
    float* out_box    = out + (size_t)ROWS * 2 + (size_t)ROWS * 1000;

    rmsnorm_kernel<<<ROWS, 256>>>(x, reward_norm_w, hn);
    gemm_kernel<false, true><<<dim3(1, ROWS/64), 256>>>(hn, reward_W, reward_b, out_reward, ROWS, 2, D_MODEL);

    rmsnorm_kernel<<<ROWS, 256>>>(x, label_norm_w, hn);
    gemm_kernel<false, true><<<dim3((1000 + 63)/64, ROWS/64), 256>>>(hn, label_W, label_b, out_label, ROWS, 1000, D_MODEL);

    rmsnorm_kernel<<<ROWS, 256>>>(x, box_norm_w, hn);
    gemm_kernel<false, true><<<dim3(1, ROWS/64), 256>>>(hn, boxh_W, boxh_b, out_box, ROWS, 4, D_MODEL);
}

// round 4
// speedup vs baseline: 2.3031x; 2.3031x over previous
#include <cuda_runtime.h>
#include <math.h>
#include <stdint.h>

#define D_MODEL 768
#define NH      12
#define DH      64
#define SEQ     512
#define BATCH   8
#define ROWS    (BATCH*SEQ)   /* 4096 */
#define DFF     3072
#define NLAYERS 12
#define LN1E4   9.210340371976184f

// ----------------------------------------------------------------------------
// Scratch (device globals; no allocation anywhere)
// ----------------------------------------------------------------------------
__device__ float g_x  [ROWS*D_MODEL];
__device__ float g_hn [ROWS*D_MODEL];
__device__ float g_qt [ROWS*D_MODEL];   // pre-rope Q, later reused as attn-out (B,L,D)
__device__ float g_kt [ROWS*D_MODEL];
__device__ float g_vt [ROWS*D_MODEL];
__device__ float g_q  [ROWS*D_MODEL];   // post-rope (B,H,L,DH)
__device__ float g_k  [ROWS*D_MODEL];
__device__ float g_sc [(size_t)BATCH*NH*SEQ*SEQ];   // 100.7 MB scores/probs
__device__ float g_gate[ROWS*DFF];      // also reused as box_sin features at embed
__device__ float g_hid [ROWS*DFF];

// ----------------------------------------------------------------------------
// TF32 helpers
// ----------------------------------------------------------------------------
__device__ __forceinline__ uint32_t f2tf32(float x) {
    uint32_t r;
    asm("cvt.rna.tf32.f32 %0, %1;" : "=r"(r) : "f"(x));
    return r;
}
__device__ __forceinline__ float f2tf32f(float x) {
    return __uint_as_float(f2tf32(x));
}

__device__ __forceinline__ void mma_tf32(float c[4],
                                         uint32_t a0, uint32_t a1, uint32_t a2, uint32_t a3,
                                         uint32_t b0, uint32_t b1) {
    asm volatile(
        "mma.sync.aligned.m16n8k8.row.col.f32.tf32.tf32.f32 "
        "{%0,%1,%2,%3}, {%4,%5,%6,%7}, {%8,%9}, {%0,%1,%2,%3};"
        : "+f"(c[0]), "+f"(c[1]), "+f"(c[2]), "+f"(c[3])
        : "r"(a0), "r"(a1), "r"(a2), "r"(a3), "r"(b0), "r"(b1));
}

// ----------------------------------------------------------------------------
// TF32 MMA GEMM: C[M,N] = A[M,K] @ B[K,N] (+C if ACC) (+bias if BIAS)
// BM=128, BN=128, BK=16, 256 threads (8 warps, 64x32 warp tiles, m16n8k8).
// Requires M % 128 == 0, K % 16 == 0, N % 4 == 0 (N otherwise arbitrary, guarded).
// ----------------------------------------------------------------------------
template<bool ACC, bool BIAS>
__global__ __launch_bounds__(256, 2)
void mma_gemm_kernel(const float* __restrict__ A, const float* __restrict__ B,
                     const float* __restrict__ bias, float* __restrict__ C,
                     int M, int N, int K)
{
    __shared__ float As[128][20];   // [m][k], stride 20 -> conflict-free frag loads
    __shared__ float Bs[16][136];   // [k][n], stride 136 -> conflict-free frag loads

    const int tid  = threadIdx.x;
    const int lane = tid & 31;
    const int warp = tid >> 5;
    const int wm   = warp >> 2;       // 0..1  (64-row slab)
    const int wn   = warp & 3;        // 0..3  (32-col slab)
    const int grp  = lane >> 2;       // 0..7
    const int tg   = lane & 3;        // 0..3

    const int m0 = blockIdx.y * 128;
    const int n0 = blockIdx.x * 128;

    // global->smem load mapping
    const int ar = tid >> 1;          // A tile row 0..127
    const int ac = (tid & 1) * 8;     // A tile col 0 or 8
    const int br = tid >> 4;          // B tile row 0..15
    const int bc = (tid & 15) * 4;    // B tile col 0..60 (plus +64)

    float4 ap0, ap1, bp0, bp1;
    {
        const float* Ap = A + (size_t)(m0 + ar) * K + ac;
        ap0 = *(const float4*)Ap;
        ap1 = *(const float4*)(Ap + 4);
        const float* Bp = B + (size_t)br * N + n0;
        bp0 = (n0 + bc      < N) ? *(const float4*)(Bp + bc)      : make_float4(0,0,0,0);
        bp1 = (n0 + bc + 64 < N) ? *(const float4*)(Bp + bc + 64) : make_float4(0,0,0,0);
    }

    float acc[4][4][4];
    #pragma unroll
    for (int i = 0; i < 4; i++)
        #pragma unroll
        for (int j = 0; j < 4; j++)
            #pragma unroll
            for (int c = 0; c < 4; c++) acc[i][j][c] = 0.f;

    for (int k0 = 0; k0 < K; k0 += 16) {
        // stage (convert to tf32 once here)
        As[ar][ac+0] = f2tf32f(ap0.x); As[ar][ac+1] = f2tf32f(ap0.y);
        As[ar][ac+2] = f2tf32f(ap0.z); As[ar][ac+3] = f2tf32f(ap0.w);
        As[ar][ac+4] = f2tf32f(ap1.x); As[ar][ac+5] = f2tf32f(ap1.y);
        As[ar][ac+6] = f2tf32f(ap1.z); As[ar][ac+7] = f2tf32f(ap1.w);
        Bs[br][bc+0]  = f2tf32f(bp0.x); Bs[br][bc+1]  = f2tf32f(bp0.y);
        Bs[br][bc+2]  = f2tf32f(bp0.z); Bs[br][bc+3]  = f2tf32f(bp0.w);
        Bs[br][bc+64] = f2tf32f(bp1.x); Bs[br][bc+65] = f2tf32f(bp1.y);
        Bs[br][bc+66] = f2tf32f(bp1.z); Bs[br][bc+67] = f2tf32f(bp1.w);
        __syncthreads();

        // prefetch next tile while computing
        if (k0 + 16 < K) {
            const float* Ap = A + (size_t)(m0 + ar) * K + (k0 + 16) + ac;
            ap0 = *(const float4*)Ap;
            ap1 = *(const float4*)(Ap + 4);
            const float* Bp = B + (size_t)(k0 + 16 + br) * N + n0;
            bp0 = (n0 + bc      < N) ? *(const float4*)(Bp + bc)      : make_float4(0,0,0,0);
            bp1 = (n0 + bc + 64 < N) ? *(const float4*)(Bp + bc + 64) : make_float4(0,0,0,0);
        }

        #pragma unroll
        for (int ks = 0; ks < 16; ks += 8) {
            uint32_t af[4][4], bf[4][2];
            #pragma unroll
            for (int mt = 0; mt < 4; mt++) {
                int mb = wm*64 + mt*16;
                af[mt][0] = __float_as_uint(As[mb + grp    ][ks + tg    ]);
                af[mt][1] = __float_as_uint(As[mb + grp + 8][ks + tg    ]);
                af[mt][2] = __float_as_uint(As[mb + grp    ][ks + tg + 4]);
                af[mt][3] = __float_as_uint(As[mb + grp + 8][ks + tg + 4]);
            }
            #pragma unroll
            for (int nt = 0; nt < 4; nt++) {
                int nb = wn*32 + nt*8;
                bf[nt][0] = __float_as_uint(Bs[ks + tg    ][nb + grp]);
                bf[nt][1] = __float_as_uint(Bs[ks + tg + 4][nb + grp]);
            }
            #pragma unroll
            for (int mt = 0; mt < 4; mt++)
                #pragma unroll
                for (int nt = 0; nt < 4; nt++)
                    mma_tf32(acc[mt][nt], af[mt][0], af[mt][1], af[mt][2], af[mt][3],
                             bf[nt][0], bf[nt][1]);
        }
        __syncthreads();
    }

    // epilogue
    #pragma unroll
    for (int mt = 0; mt < 4; mt++) {
        #pragma unroll
        for (int nt = 0; nt < 4; nt++) {
            #pragma unroll
            for (int c = 0; c < 4; c++) {
                int row = m0 + wm*64 + mt*16 + grp + ((c >= 2) ? 8 : 0);
                int col = n0 + wn*32 + nt*8 + tg*2 + (c & 1);
                if (col < N) {
                    float v = acc[mt][nt][c];
                    if (BIAS) v += bias[col];
                    size_t off = (size_t)row * N + col;
                    if (ACC) v += C[off];
                    C[off] = v;
                }
            }
        }
    }
}

// ----------------------------------------------------------------------------
// Legacy SIMT SGEMM (kept for tiny-N heads: N=2, N=4)
// ----------------------------------------------------------------------------
template<bool ACC, bool BIAS>
__global__ void gemm_kernel(const float* __restrict__ A, const float* __restrict__ B,
                            const float* __restrict__ bias, float* __restrict__ C,
                            int M, int N, int K)
{
    __shared__ float As[16][65];
    __shared__ float Bs[16][64];
    const int tid = threadIdx.x;
    const int tx = tid & 15, ty = tid >> 4;
    const int m0 = blockIdx.y * 64, n0 = blockIdx.x * 64;

    const int arow = tid >> 2;
    const int akk  = (tid & 3) * 4;
    const int bkk  = ty;
    const int bcol = tx * 4;

    float acc[4][4];
    #pragma unroll
    for (int i = 0; i < 4; i++)
        #pragma unroll
        for (int j = 0; j < 4; j++) acc[i][j] = 0.f;

    for (int k0 = 0; k0 < K; k0 += 16) {
        float4 av = *(const float4*)(A + (size_t)(m0 + arow) * K + k0 + akk);
        As[akk+0][arow] = av.x; As[akk+1][arow] = av.y;
        As[akk+2][arow] = av.z; As[akk+3][arow] = av.w;
        {
            int gn = n0 + bcol;
            const float* Bp = B + (size_t)(k0 + bkk) * N + gn;
            float4 bv;
            if (gn + 3 < N) {
                bv = *(const float4*)Bp;
            } else {
                bv.x = (gn+0 < N) ? Bp[0] : 0.f;
                bv.y = (gn+1 < N) ? Bp[1] : 0.f;
                bv.z = (gn+2 < N) ? Bp[2] : 0.f;
                bv.w = (gn+3 < N) ? Bp[3] : 0.f;
            }
            *(float4*)&Bs[bkk][bcol] = bv;
        }
        __syncthreads();
        #pragma unroll
        for (int kk = 0; kk < 16; kk++) {
            float a0 = As[kk][ty*4+0], a1 = As[kk][ty*4+1];
            float a2 = As[kk][ty*4+2], a3 = As[kk][ty*4+3];
            float4 bv = *(const float4*)&Bs[kk][tx*4];
            acc[0][0] += a0*bv.x; acc[0][1] += a0*bv.y; acc[0][2] += a0*bv.z; acc[0][3] += a0*bv.w;
            acc[1][0] += a1*bv.x; acc[1][1] += a1*bv.y; acc[1][2] += a1*bv.z; acc[1][3] += a1*bv.w;
            acc[2][0] += a2*bv.x; acc[2][1] += a2*bv.y; acc[2][2] += a2*bv.z; acc[2][3] += a2*bv.w;
            acc[3][0] += a3*bv.x; acc[3][1] += a3*bv.y; acc[3][2] += a3*bv.z; acc[3][3] += a3*bv.w;
        }
        __syncthreads();
    }

    #pragma unroll
    for (int i = 0; i < 4; i++) {
        int gm = m0 + ty*4 + i;
        #pragma unroll
        for (int j = 0; j < 4; j++) {
            int gn = n0 + tx*4 + j;
            if (gn < N) {
                float v = acc[i][j];
                if (BIAS) v += bias[gn];
                size_t off = (size_t)gm * N + gn;
                if (ACC) v += C[off];
                C[off] = v;
            }
        }
    }
}

// ----------------------------------------------------------------------------
// box Fourier features
// ----------------------------------------------------------------------------
__global__ void boxsin_kernel(const float* __restrict__ box, float* __restrict__ bs)
{
    int idx = blockIdx.x * blockDim.x + threadIdx.x;     // ROWS*4*96
    if (idx >= ROWS*4*96) return;
    int j   = idx % 96;
    int i   = (idx / 96) & 3;
    int row = idx / 384;
    float theta = expf(-(float)j * (LN1E4 / 96.f));
    float ang = box[row*4 + i] * theta;
    float s, c;
    sincosf(ang, &s, &c);
    bs[(size_t)row*D_MODEL + i*192 + 2*j    ] = c;
    bs[(size_t)row*D_MODEL + i*192 + 2*j + 1] = s;
}

// ----------------------------------------------------------------------------
// RMSNorm
// ----------------------------------------------------------------------------
__global__ void rmsnorm_kernel(const float* __restrict__ x, const float* __restrict__ w,
                               float* __restrict__ out)
{
    __shared__ float red[256];
    int row = blockIdx.x;
    const float* xr = x + (size_t)row * D_MODEL;
    float s = 0.f;
    for (int i = threadIdx.x; i < D_MODEL; i += 256) { float v = xr[i]; s += v*v; }
    red[threadIdx.x] = s; __syncthreads();
    for (int off = 128; off > 0; off >>= 1) {
        if (threadIdx.x < off) red[threadIdx.x] += red[threadIdx.x + off];
        __syncthreads();
    }
    float inv = rsqrtf(red[0] / (float)D_MODEL + 1e-6f);
    float* orow = out + (size_t)row * D_MODEL;
    for (int i = threadIdx.x; i < D_MODEL; i += 256) orow[i] = xr[i] * inv * w[i];
}

// ----------------------------------------------------------------------------
// RoPE + transpose to (B,H,L,DH)
// ----------------------------------------------------------------------------
__global__ void rope_kernel(const float* __restrict__ qt, const float* __restrict__ kt,
                            float* __restrict__ qo, float* __restrict__ ko)
{
    int idx = blockIdx.x * blockDim.x + threadIdx.x;   // BATCH*SEQ*NH*32
    if (idx >= BATCH*SEQ*NH*32) return;
    int j = idx & 31;
    int h = (idx >> 5) % NH;
    int l = (idx >> 5) / NH % SEQ;
    int b = idx / (32 * NH * SEQ);
    float theta = expf(-(float)j * (LN1E4 / 32.f));
    float ang = (float)l * theta;
    float s, c;
    sincosf(ang, &s, &c);
    size_t in  = ((size_t)(b*SEQ + l)) * D_MODEL + h*DH + 2*j;
    size_t out = ((size_t)((b*NH + h)*SEQ + l)) * DH + 2*j;
    float qr = qt[in], qi = qt[in+1];
    qo[out]   = qr*c - qi*s;
    qo[out+1] = qr*s + qi*c;
    float kr = kt[in], ki = kt[in+1];
    ko[out]   = kr*c - ki*s;
    ko[out+1] = kr*s + ki*c;
}

// ----------------------------------------------------------------------------
// Scores: S[bh, m, n] = (Q . K)/8, skip strictly-upper tiles
// ----------------------------------------------------------------------------
__global__ void attn_scores_kernel(const float* __restrict__ Q, const float* __restrict__ Kd,
                                   float* __restrict__ S)
{
    int bh = blockIdx.z;
    int m0 = blockIdx.y * 64, n0 = blockIdx.x * 64;
    if (n0 > m0 + 63) return;
    const float* Qb = Q  + (size_t)bh * SEQ * DH;
    const float* Kb = Kd + (size_t)bh * SEQ * DH;
    float* Sb = S + (size_t)bh * SEQ * SEQ;

    __shared__ float Qs[16][65];
    __shared__ float Ks[16][65];
    const int tid = threadIdx.x;
    const int tx = tid & 15, ty = tid >> 4;
    const int row = tid >> 2, kk4 = (tid & 3) * 4;

    float acc[4][4];
    #pragma unroll
    for (int i = 0; i < 4; i++)
        #pragma unroll
        for (int j = 0; j < 4; j++) acc[i][j] = 0.f;

    for (int k0 = 0; k0 < DH; k0 += 16) {
        float4 qv = *(const float4*)(Qb + (size_t)(m0 + row) * DH + k0 + kk4);
        Qs[kk4+0][row] = qv.x; Qs[kk4+1][row] = qv.y;
        Qs[kk4+2][row] = qv.z; Qs[kk4+3][row] = qv.w;
        float4 kv = *(const float4*)(Kb + (size_t)(n0 + row) * DH + k0 + kk4);
        Ks[kk4+0][row] = kv.x; Ks[kk4+1][row] = kv.y;
        Ks[kk4+2][row] = kv.z; Ks[kk4+3][row] = kv.w;
        __syncthreads();
        #pragma unroll
        for (int kk = 0; kk < 16; kk++) {
            float a0 = Qs[kk][ty*4+0], a1 = Qs[kk][ty*4+1];
            float a2 = Qs[kk][ty*4+2], a3 = Qs[kk][ty*4+3];
            float b0 = Ks[kk][tx*4+0], b1 = Ks[kk][tx*4+1];
            float b2 = Ks[kk][tx*4+2], b3 = Ks[kk][tx*4+3];
            acc[0][0] += a0*b0; acc[0][1] += a0*b1; acc[0][2] += a0*b2; acc[0][3] += a0*b3;
            acc[1][0] += a1*b0; acc[1][1] += a1*b1; acc[1][2] += a1*b2; acc[1][3] += a1*b3;
            acc[2][0] += a2*b0; acc[2][1] += a2*b1; acc[2][2] += a2*b2; acc[2][3] += a2*b3;
            acc[3][0] += a3*b0; acc[3][1] += a3*b1; acc[3][2] += a3*b2; acc[3][3] += a3*b3;
        }
        __syncthreads();
    }
    const float inv = 0.125f;
    #pragma unroll
    for (int i = 0; i < 4; i++)
        #pragma unroll
        for (int j = 0; j < 4; j++)
            Sb[(size_t)(m0 + ty*4 + i) * SEQ + n0 + tx*4 + j] = acc[i][j] * inv;
}

// ----------------------------------------------------------------------------
// Causal row softmax
// ----------------------------------------------------------------------------
__global__ void softmax_kernel(float* __restrict__ S)
{
    __shared__ float red[128];
    int row = blockIdx.x;
    int l = row & (SEQ - 1);
    float* Sr = S + (size_t)row * SEQ;
    int t = threadIdx.x;

    float mx = -1e30f;
    for (int i = t; i <= l; i += 128) mx = fmaxf(mx, Sr[i]);
    red[t] = mx; __syncthreads();
    for (int off = 64; off > 0; off >>= 1) {
        if (t < off) red[t] = fmaxf(red[t], red[t + off]);
        __syncthreads();
    }
    mx = red[0]; __syncthreads();

    float e[4];
    float sum = 0.f;
    #pragma unroll
    for (int j = 0; j < 4; j++) {
        int i = t + j * 128;
        e[j] = (i <= l) ? expf(Sr[i] - mx) : 0.f;
        sum += e[j];
    }
    red[t] = sum; __syncthreads();
    for (int off = 64; off > 0; off >>= 1) {
        if (t < off) red[t] += red[t + off];
        __syncthreads();
    }
    float invs = 1.f / red[0];
    #pragma unroll
    for (int j = 0; j < 4; j++) {
        int i = t + j * 128;
        Sr[i] = e[j] * invs;
    }
}

// ----------------------------------------------------------------------------
// AV
// ----------------------------------------------------------------------------
__global__ void attn_av_kernel(const float* __restrict__ P, const float* __restrict__ V,
                               float* __restrict__ O)
{
    int bh = blockIdx.y;
    int m0 = blockIdx.x * 64;
    int b = bh / NH, h = bh % NH;
    const float* Pb = P + (size_t)bh * SEQ * SEQ;

    __shared__ float Ps[16][65];
    __shared__ float Vs[16][64];
    const int tid = threadIdx.x;
    const int tx = tid & 15, ty = tid >> 4;
    const int prow = tid >> 2, pkk = (tid & 3) * 4;

    float acc[4][4];
    #pragma unroll
    for (int i = 0; i < 4; i++)
        #pragma unroll
        for (int j = 0; j < 4; j++) acc[i][j] = 0.f;

    int kend = m0 + 64;
    for (int k0 = 0; k0 < kend; k0 += 16) {
        float4 pv = *(const float4*)(Pb + (size_t)(m0 + prow) * SEQ + k0 + pkk);
        Ps[pkk+0][prow] = pv.x; Ps[pkk+1][prow] = pv.y;
        Ps[pkk+2][prow] = pv.z; Ps[pkk+3][prow] = pv.w;
        float4 vv = *(const float4*)(V + ((size_t)(b*SEQ + k0 + ty)) * D_MODEL + h*DH + tx*4);
        *(float4*)&Vs[ty][tx*4] = vv;
        __syncthreads();
        #pragma unroll
        for (int kk = 0; kk < 16; kk++) {
            float a0 = Ps[kk][ty*4+0], a1 = Ps[kk][ty*4+1];
            float a2 = Ps[kk][ty*4+2], a3 = Ps[kk][ty*4+3];
            float4 bv = *(const float4*)&Vs[kk][tx*4];
            acc[0][0] += a0*bv.x; acc[0][1] += a0*bv.y; acc[0][2] += a0*bv.z; acc[0][3] += a0*bv.w;
            acc[1][0] += a1*bv.x; acc[1][1] += a1*bv.y; acc[1][2] += a1*bv.z; acc[1][3] += a1*bv.w;
            acc[2][0] += a2*bv.x; acc[2][1] += a2*bv.y; acc[2][2] += a2*bv.z; acc[2][3] += a2*bv.w;
            acc[3][0] += a3*bv.x; acc[3][1] += a3*bv.y; acc[3][2] += a3*bv.z; acc[3][3] += a3*bv.w;
        }
        __syncthreads();
    }
    #pragma unroll
    for (int i = 0; i < 4; i++)
        #pragma unroll
        for (int j = 0; j < 4; j++)
            O[((size_t)(b*SEQ + m0 + ty*4 + i)) * D_MODEL + h*DH + tx*4 + j] = acc[i][j];
}

// ----------------------------------------------------------------------------
// SiLU-mul
// ----------------------------------------------------------------------------
__global__ void silu_mul_kernel(float* __restrict__ g, const float* __restrict__ h, int n)
{
    for (int i = blockIdx.x * blockDim.x + threadIdx.x; i < n; i += gridDim.x * blockDim.x) {
        float x = g[i];
        g[i] = (x / (1.f + expf(-x))) * h[i];
    }
}

// ----------------------------------------------------------------------------
// Launch
// ----------------------------------------------------------------------------
extern "C" void kernel_launch(void* const* d_in, const int* in_sizes, int n_in,
                              void* d_out, int out_size)
{
    const float* patch        = (const float*)d_in[0];
    const float* box          = (const float*)d_in[1];
    const float* patch_W      = (const float*)d_in[2];
    const float* patch_b      = (const float*)d_in[3];
    const float* box_W        = (const float*)d_in[4];
    const float* box_b        = (const float*)d_in[5];
    const float* Wq           = (const float*)d_in[6];
    const float* Wk           = (const float*)d_in[7];
    const float* Wv           = (const float*)d_in[8];
    const float* Wo           = (const float*)d_in[9];
    const float* attn_norm_w  = (const float*)d_in[10];
    const float* gate_W       = (const float*)d_in[11];
    const float* hidden_W     = (const float*)d_in[12];
    const float* ffn_out_W    = (const float*)d_in[13];
    const float* ffn_norm_w   = (const float*)d_in[14];
    const float* reward_norm_w= (const float*)d_in[15];
    const float* reward_W     = (const float*)d_in[16];
    const float* reward_b     = (const float*)d_in[17];
    const float* label_norm_w = (const float*)d_in[18];
    const float* label_W      = (const float*)d_in[19];
    const float* label_b      = (const float*)d_in[20];
    const float* box_norm_w   = (const float*)d_in[21];
    const float* boxh_W       = (const float*)d_in[22];
    const float* boxh_b       = (const float*)d_in[23];
    float* out = (float*)d_out;

    float *x, *hn, *qt, *kt, *vt, *q, *k, *sc, *gate, *hid;
    { void* p;
      cudaGetSymbolAddress(&p, g_x);    x    = (float*)p;
      cudaGetSymbolAddress(&p, g_hn);   hn   = (float*)p;
      cudaGetSymbolAddress(&p, g_qt);   qt   = (float*)p;
      cudaGetSymbolAddress(&p, g_kt);   kt   = (float*)p;
      cudaGetSymbolAddress(&p, g_vt);   vt   = (float*)p;
      cudaGetSymbolAddress(&p, g_q);    q    = (float*)p;
      cudaGetSymbolAddress(&p, g_k);    k    = (float*)p;
      cudaGetSymbolAddress(&p, g_sc);   sc   = (float*)p;
      cudaGetSymbolAddress(&p, g_gate); gate = (float*)p;
      cudaGetSymbolAddress(&p, g_hid);  hid  = (float*)p;
    }

    const dim3 m768 (D_MODEL/128, ROWS/128);   // (6, 32)
    const dim3 m3072(DFF/128,     ROWS/128);   // (24, 32)
    const dim3 m1000((1000+127)/128, ROWS/128);

    // ---- Embedding ----
    {
        int n = ROWS * 4 * 96;
        boxsin_kernel<<<(n + 255) / 256, 256>>>(box, gate);   // gate reused as box_sin
    }
    mma_gemm_kernel<false, true><<<m768, 256>>>(patch, patch_W, patch_b, x, ROWS, D_MODEL, D_MODEL);
    mma_gemm_kernel<true,  true><<<m768, 256>>>(gate,  box_W,   box_b,   x, ROWS, D_MODEL, D_MODEL);

    // ---- Layers ----
    for (int L = 0; L < NLAYERS; L++) {
        const float* wq  = Wq + (size_t)L * D_MODEL * D_MODEL;
        const float* wk  = Wk + (size_t)L * D_MODEL * D_MODEL;
        const float* wv  = Wv + (size_t)L * D_MODEL * D_MODEL;
        const float* wo  = Wo + (size_t)L * D_MODEL * D_MODEL;
        const float* anw = attn_norm_w + (size_t)L * D_MODEL;
        const float* gw  = gate_W   + (size_t)L * D_MODEL * DFF;
        const float* hw  = hidden_W + (size_t)L * D_MODEL * DFF;
        const float* ow  = ffn_out_W+ (size_t)L * DFF * D_MODEL;
        const float* fnw = ffn_norm_w + (size_t)L * D_MODEL;

        // attention
        rmsnorm_kernel<<<ROWS, 256>>>(x, anw, hn);
        mma_gemm_kernel<false, false><<<m768, 256>>>(hn, wq, nullptr, qt, ROWS, D_MODEL, D_MODEL);
        mma_gemm_kernel<false, false><<<m768, 256>>>(hn, wk, nullptr, kt, ROWS, D_MODEL, D_MODEL);
        mma_gemm_kernel<false, false><<<m768, 256>>>(hn, wv, nullptr, vt, ROWS, D_MODEL, D_MODEL);
        {
            int n = BATCH * SEQ * NH * 32;
            rope_kernel<<<(n + 255) / 256, 256>>>(qt, kt, q, k);
        }
        attn_scores_kernel<<<dim3(SEQ/64, SEQ/64, BATCH*NH), 256>>>(q, k, sc);
        softmax_kernel<<<BATCH*NH*SEQ, 128>>>(sc);
        attn_av_kernel<<<dim3(SEQ/64, BATCH*NH), 256>>>(sc, vt, qt);   // qt reused as O
        mma_gemm_kernel<true, false><<<m768, 256>>>(qt, wo, nullptr, x, ROWS, D_MODEL, D_MODEL);

        // FFN
        rmsnorm_kernel<<<ROWS, 256>>>(x, fnw, hn);
        mma_gemm_kernel<false, false><<<m3072, 256>>>(hn, gw, nullptr, gate, ROWS, DFF, D_MODEL);
        mma_gemm_kernel<false, false><<<m3072, 256>>>(hn, hw, nullptr, hid,  ROWS, DFF, D_MODEL);
        silu_mul_kernel<<<2048, 256>>>(gate, hid, ROWS * DFF);
        mma_gemm_kernel<true, false><<<m768, 256>>>(gate, ow, nullptr, x, ROWS, D_MODEL, DFF);
    }

    // ---- Heads ----
    float* out_reward = out;
    float* out_label  = out + (size_t)ROWS * 2;
    float* out_box    = out + (size_t)ROWS * 2 + (size_t)ROWS * 1000;

    rmsnorm_kernel<<<ROWS, 256>>>(x, reward_norm_w, hn);
    gemm_kernel<false, true><<<dim3(1, ROWS/64), 256>>>(hn, reward_W, reward_b, out_reward, ROWS, 2, D_MODEL);

    rmsnorm_kernel<<<ROWS, 256>>>(x, label_norm_w, hn);
    mma_gemm_kernel<false, true><<<m1000, 256>>>(hn, label_W, label_b, out_label, ROWS, 1000, D_MODEL);

    rmsnorm_kernel<<<ROWS, 256>>>(x, box_norm_w, hn);
    gemm_kernel<false, true><<<dim3(1, ROWS/64), 256>>>(hn, boxh_W, boxh_b, out_box, ROWS, 4, D_MODEL);
}

// round 5
// speedup vs baseline: 2.3049x; 1.0008x over previous
#include <cuda_runtime.h>
#include <math.h>
#include <stdint.h>

#define D_MODEL 768
#define NH      12
#define DH      64
#define SEQ     512
#define BATCH   8
#define ROWS    (BATCH*SEQ)   /* 4096 */
#define DFF     3072
#define NLAYERS 12
#define LN1E4   9.210340371976184f

// ----------------------------------------------------------------------------
// Scratch (device globals; no allocation anywhere)
// ----------------------------------------------------------------------------
__device__ float g_x  [ROWS*D_MODEL];
__device__ float g_hn [ROWS*D_MODEL];
__device__ float g_qt [ROWS*D_MODEL];   // pre-rope Q, later reused as attn-out (B,L,D)
__device__ float g_kt [ROWS*D_MODEL];
__device__ float g_vt [ROWS*D_MODEL];
__device__ float g_q  [ROWS*D_MODEL];   // post-rope (B,H,L,DH)
__device__ float g_k  [ROWS*D_MODEL];
__device__ float g_sc [(size_t)BATCH*NH*SEQ*SEQ];   // 100.7 MB scores/probs
__device__ float g_gate[ROWS*DFF];      // also reused as box_sin features at embed
__device__ float g_hid [ROWS*DFF];

// ----------------------------------------------------------------------------
// TF32 helpers
// ----------------------------------------------------------------------------
__device__ __forceinline__ uint32_t f2tf32(float x) {
    uint32_t r;
    asm("cvt.rna.tf32.f32 %0, %1;" : "=r"(r) : "f"(x));
    return r;
}
__device__ __forceinline__ float f2tf32f(float x) {
    return __uint_as_float(f2tf32(x));
}

__device__ __forceinline__ void mma_tf32(float c[4],
                                         uint32_t a0, uint32_t a1, uint32_t a2, uint32_t a3,
                                         uint32_t b0, uint32_t b1) {
    asm volatile(
        "mma.sync.aligned.m16n8k8.row.col.f32.tf32.tf32.f32 "
        "{%0,%1,%2,%3}, {%4,%5,%6,%7}, {%8,%9}, {%0,%1,%2,%3};"
        : "+f"(c[0]), "+f"(c[1]), "+f"(c[2]), "+f"(c[3])
        : "r"(a0), "r"(a1), "r"(a2), "r"(a3), "r"(b0), "r"(b1));
}

// ----------------------------------------------------------------------------
// TF32 MMA GEMM: C[M,N] = A[M,K] @ B[K,N] (+C if ACC) (+bias if BIAS)
// BM=128, BN=128, BK=16, 256 threads (8 warps, 64x32 warp tiles, m16n8k8).
// Requires M % 128 == 0, K % 16 == 0, N % 4 == 0 (N otherwise arbitrary, guarded).
// ----------------------------------------------------------------------------
template<bool ACC, bool BIAS>
__global__ __launch_bounds__(256, 2)
void mma_gemm_kernel(const float* __restrict__ A, const float* __restrict__ B,
                     const float* __restrict__ bias, float* __restrict__ C,
                     int M, int N, int K)
{
    __shared__ float As[128][20];   // [m][k], stride 20 -> conflict-free frag loads
    __shared__ float Bs[16][136];   // [k][n], stride 136 -> conflict-free frag loads

    const int tid  = threadIdx.x;
    const int lane = tid & 31;
    const int warp = tid >> 5;
    const int wm   = warp >> 2;       // 0..1  (64-row slab)
    const int wn   = warp & 3;        // 0..3  (32-col slab)
    const int grp  = lane >> 2;       // 0..7
    const int tg   = lane & 3;        // 0..3

    const int m0 = blockIdx.y * 128;
    const int n0 = blockIdx.x * 128;

    // global->smem load mapping
    const int ar = tid >> 1;          // A tile row 0..127
    const int ac = (tid & 1) * 8;     // A tile col 0 or 8
    const int br = tid >> 4;          // B tile row 0..15
    const int bc = (tid & 15) * 4;    // B tile col 0..60 (plus +64)

    float4 ap0, ap1, bp0, bp1;
    {
        const float* Ap = A + (size_t)(m0 + ar) * K + ac;
        ap0 = *(const float4*)Ap;
        ap1 = *(const float4*)(Ap + 4);
        const float* Bp = B + (size_t)br * N + n0;
        bp0 = (n0 + bc      < N) ? *(const float4*)(Bp + bc)      : make_float4(0,0,0,0);
        bp1 = (n0 + bc + 64 < N) ? *(const float4*)(Bp + bc + 64) : make_float4(0,0,0,0);
    }

    float acc[4][4][4];
    #pragma unroll
    for (int i = 0; i < 4; i++)
        #pragma unroll
        for (int j = 0; j < 4; j++)
            #pragma unroll
            for (int c = 0; c < 4; c++) acc[i][j][c] = 0.f;

    for (int k0 = 0; k0 < K; k0 += 16) {
        // stage (convert to tf32 once here)
        As[ar][ac+0] = f2tf32f(ap0.x); As[ar][ac+1] = f2tf32f(ap0.y);
        As[ar][ac+2] = f2tf32f(ap0.z); As[ar][ac+3] = f2tf32f(ap0.w);
        As[ar][ac+4] = f2tf32f(ap1.x); As[ar][ac+5] = f2tf32f(ap1.y);
        As[ar][ac+6] = f2tf32f(ap1.z); As[ar][ac+7] = f2tf32f(ap1.w);
        Bs[br][bc+0]  = f2tf32f(bp0.x); Bs[br][bc+1]  = f2tf32f(bp0.y);
        Bs[br][bc+2]  = f2tf32f(bp0.z); Bs[br][bc+3]  = f2tf32f(bp0.w);
        Bs[br][bc+64] = f2tf32f(bp1.x); Bs[br][bc+65] = f2tf32f(bp1.y);
        Bs[br][bc+66] = f2tf32f(bp1.z); Bs[br][bc+67] = f2tf32f(bp1.w);
        __syncthreads();

        // prefetch next tile while computing
        if (k0 + 16 < K) {
            const float* Ap = A + (size_t)(m0 + ar) * K + (k0 + 16) + ac;
            ap0 = *(const float4*)Ap;
            ap1 = *(const float4*)(Ap + 4);
            const float* Bp = B + (size_t)(k0 + 16 + br) * N + n0;
            bp0 = (n0 + bc      < N) ? *(const float4*)(Bp + bc)      : make_float4(0,0,0,0);
            bp1 = (n0 + bc + 64 < N) ? *(const float4*)(Bp + bc + 64) : make_float4(0,0,0,0);
        }

        #pragma unroll
        for (int ks = 0; ks < 16; ks += 8) {
            uint32_t af[4][4], bf[4][2];
            #pragma unroll
            for (int mt = 0; mt < 4; mt++) {
                int mb = wm*64 + mt*16;
                af[mt][0] = __float_as_uint(As[mb + grp    ][ks + tg    ]);
                af[mt][1] = __float_as_uint(As[mb + grp + 8][ks + tg    ]);
                af[mt][2] = __float_as_uint(As[mb + grp    ][ks + tg + 4]);
                af[mt][3] = __float_as_uint(As[mb + grp + 8][ks + tg + 4]);
            }
            #pragma unroll
            for (int nt = 0; nt < 4; nt++) {
                int nb = wn*32 + nt*8;
                bf[nt][0] = __float_as_uint(Bs[ks + tg    ][nb + grp]);
                bf[nt][1] = __float_as_uint(Bs[ks + tg + 4][nb + grp]);
            }
            #pragma unroll
            for (int mt = 0; mt < 4; mt++)
                #pragma unroll
                for (int nt = 0; nt < 4; nt++)
                    mma_tf32(acc[mt][nt], af[mt][0], af[mt][1], af[mt][2], af[mt][3],
                             bf[nt][0], bf[nt][1]);
        }
        __syncthreads();
    }

    // epilogue
    #pragma unroll
    for (int mt = 0; mt < 4; mt++) {
        #pragma unroll
        for (int nt = 0; nt < 4; nt++) {
            #pragma unroll
            for (int c = 0; c < 4; c++) {
                int row = m0 + wm*64 + mt*16 + grp + ((c >= 2) ? 8 : 0);
                int col = n0 + wn*32 + nt*8 + tg*2 + (c & 1);
                if (col < N) {
                    float v = acc[mt][nt][c];
                    if (BIAS) v += bias[col];
                    size_t off = (size_t)row * N + col;
                    if (ACC) v += C[off];
                    C[off] = v;
                }
            }
        }
    }
}

// ----------------------------------------------------------------------------
// Legacy SIMT SGEMM (kept for tiny-N heads: N=2, N=4)
// ----------------------------------------------------------------------------
template<bool ACC, bool BIAS>
__global__ void gemm_kernel(const float* __restrict__ A, const float* __restrict__ B,
                            const float* __restrict__ bias, float* __restrict__ C,
                            int M, int N, int K)
{
    __shared__ float As[16][65];
    __shared__ float Bs[16][64];
    const int tid = threadIdx.x;
    const int tx = tid & 15, ty = tid >> 4;
    const int m0 = blockIdx.y * 64, n0 = blockIdx.x * 64;

    const int arow = tid >> 2;
    const int akk  = (tid & 3) * 4;
    const int bkk  = ty;
    const int bcol = tx * 4;

    float acc[4][4];
    #pragma unroll
    for (int i = 0; i < 4; i++)
        #pragma unroll
        for (int j = 0; j < 4; j++) acc[i][j] = 0.f;

    for (int k0 = 0; k0 < K; k0 += 16) {
        float4 av = *(const float4*)(A + (size_t)(m0 + arow) * K + k0 + akk);
        As[akk+0][arow] = av.x; As[akk+1][arow] = av.y;
        As[akk+2][arow] = av.z; As[akk+3][arow] = av.w;
        {
            int gn = n0 + bcol;
            const float* Bp = B + (size_t)(k0 + bkk) * N + gn;
            float4 bv;
            if (gn + 3 < N) {
                bv = *(const float4*)Bp;
            } else {
                bv.x = (gn+0 < N) ? Bp[0] : 0.f;
                bv.y = (gn+1 < N) ? Bp[1] : 0.f;
                bv.z = (gn+2 < N) ? Bp[2] : 0.f;
                bv.w = (gn+3 < N) ? Bp[3] : 0.f;
            }
            *(float4*)&Bs[bkk][bcol] = bv;
        }
        __syncthreads();
        #pragma unroll
        for (int kk = 0; kk < 16; kk++) {
            float a0 = As[kk][ty*4+0], a1 = As[kk][ty*4+1];
            float a2 = As[kk][ty*4+2], a3 = As[kk][ty*4+3];
            float4 bv = *(const float4*)&Bs[kk][tx*4];
            acc[0][0] += a0*bv.x; acc[0][1] += a0*bv.y; acc[0][2] += a0*bv.z; acc[0][3] += a0*bv.w;
            acc[1][0] += a1*bv.x; acc[1][1] += a1*bv.y; acc[1][2] += a1*bv.z; acc[1][3] += a1*bv.w;
            acc[2][0] += a2*bv.x; acc[2][1] += a2*bv.y; acc[2][2] += a2*bv.z; acc[2][3] += a2*bv.w;
            acc[3][0] += a3*bv.x; acc[3][1] += a3*bv.y; acc[3][2] += a3*bv.z; acc[3][3] += a3*bv.w;
        }
        __syncthreads();
    }

    #pragma unroll
    for (int i = 0; i < 4; i++) {
        int gm = m0 + ty*4 + i;
        #pragma unroll
        for (int j = 0; j < 4; j++) {
            int gn = n0 + tx*4 + j;
            if (gn < N) {
                float v = acc[i][j];
                if (BIAS) v += bias[gn];
                size_t off = (size_t)gm * N + gn;
                if (ACC) v += C[off];
                C[off] = v;
            }
        }
    }
}

// ----------------------------------------------------------------------------
// box Fourier features
// ----------------------------------------------------------------------------
__global__ void boxsin_kernel(const float* __restrict__ box, float* __restrict__ bs)
{
    int idx = blockIdx.x * blockDim.x + threadIdx.x;     // ROWS*4*96
    if (idx >= ROWS*4*96) return;
    int j   = idx % 96;
    int i   = (idx / 96) & 3;
    int row = idx / 384;
    float theta = expf(-(float)j * (LN1E4 / 96.f));
    float ang = box[row*4 + i] * theta;
    float s, c;
    sincosf(ang, &s, &c);
    bs[(size_t)row*D_MODEL + i*192 + 2*j    ] = c;
    bs[(size_t)row*D_MODEL + i*192 + 2*j + 1] = s;
}

// ----------------------------------------------------------------------------
// RMSNorm
// ----------------------------------------------------------------------------
__global__ void rmsnorm_kernel(const float* __restrict__ x, const float* __restrict__ w,
                               float* __restrict__ out)
{
    __shared__ float red[256];
    int row = blockIdx.x;
    const float* xr = x + (size_t)row * D_MODEL;
    float s = 0.f;
    for (int i = threadIdx.x; i < D_MODEL; i += 256) { float v = xr[i]; s += v*v; }
    red[threadIdx.x] = s; __syncthreads();
    for (int off = 128; off > 0; off >>= 1) {
        if (threadIdx.x < off) red[threadIdx.x] += red[threadIdx.x + off];
        __syncthreads();
    }
    float inv = rsqrtf(red[0] / (float)D_MODEL + 1e-6f);
    float* orow = out + (size_t)row * D_MODEL;
    for (int i = threadIdx.x; i < D_MODEL; i += 256) orow[i] = xr[i] * inv * w[i];
}

// ----------------------------------------------------------------------------
// RoPE + transpose to (B,H,L,DH)
// ----------------------------------------------------------------------------
__global__ void rope_kernel(const float* __restrict__ qt, const float* __restrict__ kt,
                            float* __restrict__ qo, float* __restrict__ ko)
{
    int idx = blockIdx.x * blockDim.x + threadIdx.x;   // BATCH*SEQ*NH*32
    if (idx >= BATCH*SEQ*NH*32) return;
    int j = idx & 31;
    int h = (idx >> 5) % NH;
    int l = (idx >> 5) / NH % SEQ;
    int b = idx / (32 * NH * SEQ);
    float theta = expf(-(float)j * (LN1E4 / 32.f));
    float ang = (float)l * theta;
    float s, c;
    sincosf(ang, &s, &c);
    size_t in  = ((size_t)(b*SEQ + l)) * D_MODEL + h*DH + 2*j;
    size_t out = ((size_t)((b*NH + h)*SEQ + l)) * DH + 2*j;
    float qr = qt[in], qi = qt[in+1];
    qo[out]   = qr*c - qi*s;
    qo[out+1] = qr*s + qi*c;
    float kr = kt[in], ki = kt[in+1];
    ko[out]   = kr*c - ki*s;
    ko[out+1] = kr*s + ki*c;
}

// ----------------------------------------------------------------------------
// Scores: S[bh, m, n] = (Q . K)/8, skip strictly-upper tiles
// ----------------------------------------------------------------------------
__global__ void attn_scores_kernel(const float* __restrict__ Q, const float* __restrict__ Kd,
                                   float* __restrict__ S)
{
    int bh = blockIdx.z;
    int m0 = blockIdx.y * 64, n0 = blockIdx.x * 64;
    if (n0 > m0 + 63) return;
    const float* Qb = Q  + (size_t)bh * SEQ * DH;
    const float* Kb = Kd + (size_t)bh * SEQ * DH;
    float* Sb = S + (size_t)bh * SEQ * SEQ;

    __shared__ float Qs[16][65];
    __shared__ float Ks[16][65];
    const int tid = threadIdx.x;
    const int tx = tid & 15, ty = tid >> 4;
    const int row = tid >> 2, kk4 = (tid & 3) * 4;

    float acc[4][4];
    #pragma unroll
    for (int i = 0; i < 4; i++)
        #pragma unroll
        for (int j = 0; j < 4; j++) acc[i][j] = 0.f;

    for (int k0 = 0; k0 < DH; k0 += 16) {
        float4 qv = *(const float4*)(Qb + (size_t)(m0 + row) * DH + k0 + kk4);
        Qs[kk4+0][row] = qv.x; Qs[kk4+1][row] = qv.y;
        Qs[kk4+2][row] = qv.z; Qs[kk4+3][row] = qv.w;
        float4 kv = *(const float4*)(Kb + (size_t)(n0 + row) * DH + k0 + kk4);
        Ks[kk4+0][row] = kv.x; Ks[kk4+1][row] = kv.y;
        Ks[kk4+2][row] = kv.z; Ks[kk4+3][row] = kv.w;
        __syncthreads();
        #pragma unroll
        for (int kk = 0; kk < 16; kk++) {
            float a0 = Qs[kk][ty*4+0], a1 = Qs[kk][ty*4+1];
            float a2 = Qs[kk][ty*4+2], a3 = Qs[kk][ty*4+3];
            float b0 = Ks[kk][tx*4+0], b1 = Ks[kk][tx*4+1];
            float b2 = Ks[kk][tx*4+2], b3 = Ks[kk][tx*4+3];
            acc[0][0] += a0*b0; acc[0][1] += a0*b1; acc[0][2] += a0*b2; acc[0][3] += a0*b3;
            acc[1][0] += a1*b0; acc[1][1] += a1*b1; acc[1][2] += a1*b2; acc[1][3] += a1*b3;
            acc[2][0] += a2*b0; acc[2][1] += a2*b1; acc[2][2] += a2*b2; acc[2][3] += a2*b3;
            acc[3][0] += a3*b0; acc[3][1] += a3*b1; acc[3][2] += a3*b2; acc[3][3] += a3*b3;
        }
        __syncthreads();
    }
    const float inv = 0.125f;
    #pragma unroll
    for (int i = 0; i < 4; i++)
        #pragma unroll
        for (int j = 0; j < 4; j++)
            Sb[(size_t)(m0 + ty*4 + i) * SEQ + n0 + tx*4 + j] = acc[i][j] * inv;
}

// ----------------------------------------------------------------------------
// Causal row softmax
// ----------------------------------------------------------------------------
__global__ void softmax_kernel(float* __restrict__ S)
{
    __shared__ float red[128];
    int row = blockIdx.x;
    int l = row & (SEQ - 1);
    float* Sr = S + (size_t)row * SEQ;
    int t = threadIdx.x;

    float mx = -1e30f;
    for (int i = t; i <= l; i += 128) mx = fmaxf(mx, Sr[i]);
    red[t] = mx; __syncthreads();
    for (int off = 64; off > 0; off >>= 1) {
        if (t < off) red[t] = fmaxf(red[t], red[t + off]);
        __syncthreads();
    }
    mx = red[0]; __syncthreads();

    float e[4];
    float sum = 0.f;
    #pragma unroll
    for (int j = 0; j < 4; j++) {
        int i = t + j * 128;
        e[j] = (i <= l) ? expf(Sr[i] - mx) : 0.f;
        sum += e[j];
    }
    red[t] = sum; __syncthreads();
    for (int off = 64; off > 0; off >>= 1) {
        if (t < off) red[t] += red[t + off];
        __syncthreads();
    }
    float invs = 1.f / red[0];
    #pragma unroll
    for (int j = 0; j < 4; j++) {
        int i = t + j * 128;
        Sr[i] = e[j] * invs;
    }
}

// ----------------------------------------------------------------------------
// AV
// ----------------------------------------------------------------------------
__global__ void attn_av_kernel(const float* __restrict__ P, const float* __restrict__ V,
                               float* __restrict__ O)
{
    int bh = blockIdx.y;
    int m0 = blockIdx.x * 64;
    int b = bh / NH, h = bh % NH;
    const float* Pb = P + (size_t)bh * SEQ * SEQ;

    __shared__ float Ps[16][65];
    __shared__ float Vs[16][64];
    const int tid = threadIdx.x;
    const int tx = tid & 15, ty = tid >> 4;
    const int prow = tid >> 2, pkk = (tid & 3) * 4;

    float acc[4][4];
    #pragma unroll
    for (int i = 0; i < 4; i++)
        #pragma unroll
        for (int j = 0; j < 4; j++) acc[i][j] = 0.f;

    int kend = m0 + 64;
    for (int k0 = 0; k0 < kend; k0 += 16) {
        float4 pv = *(const float4*)(Pb + (size_t)(m0 + prow) * SEQ + k0 + pkk);
        Ps[pkk+0][prow] = pv.x; Ps[pkk+1][prow] = pv.y;
        Ps[pkk+2][prow] = pv.z; Ps[pkk+3][prow] = pv.w;
        float4 vv = *(const float4*)(V + ((size_t)(b*SEQ + k0 + ty)) * D_MODEL + h*DH + tx*4);
        *(float4*)&Vs[ty][tx*4] = vv;
        __syncthreads();
        #pragma unroll
        for (int kk = 0; kk < 16; kk++) {
            float a0 = Ps[kk][ty*4+0], a1 = Ps[kk][ty*4+1];
            float a2 = Ps[kk][ty*4+2], a3 = Ps[kk][ty*4+3];
            float4 bv = *(const float4*)&Vs[kk][tx*4];
            acc[0][0] += a0*bv.x; acc[0][1] += a0*bv.y; acc[0][2] += a0*bv.z; acc[0][3] += a0*bv.w;
            acc[1][0] += a1*bv.x; acc[1][1] += a1*bv.y; acc[1][2] += a1*bv.z; acc[1][3] += a1*bv.w;
            acc[2][0] += a2*bv.x; acc[2][1] += a2*bv.y; acc[2][2] += a2*bv.z; acc[2][3] += a2*bv.w;
            acc[3][0] += a3*bv.x; acc[3][1] += a3*bv.y; acc[3][2] += a3*bv.z; acc[3][3] += a3*bv.w;
        }
        __syncthreads();
    }
    #pragma unroll
    for (int i = 0; i < 4; i++)
        #pragma unroll
        for (int j = 0; j < 4; j++)
            O[((size_t)(b*SEQ + m0 + ty*4 + i)) * D_MODEL + h*DH + tx*4 + j] = acc[i][j];
}

// ----------------------------------------------------------------------------
// SiLU-mul
// ----------------------------------------------------------------------------
__global__ void silu_mul_kernel(float* __restrict__ g, const float* __restrict__ h, int n)
{
    for (int i = blockIdx.x * blockDim.x + threadIdx.x; i < n; i += gridDim.x * blockDim.x) {
        float x = g[i];
        g[i] = (x / (1.f + expf(-x))) * h[i];
    }
}

// ----------------------------------------------------------------------------
// Launch
// ----------------------------------------------------------------------------
extern "C" void kernel_launch(void* const* d_in, const int* in_sizes, int n_in,
                              void* d_out, int out_size)
{
    const float* patch        = (const float*)d_in[0];
    const float* box          = (const float*)d_in[1];
    const float* patch_W      = (const float*)d_in[2];
    const float* patch_b      = (const float*)d_in[3];
    const float* box_W        = (const float*)d_in[4];
    const float* box_b        = (const float*)d_in[5];
    const float* Wq           = (const float*)d_in[6];
    const float* Wk           = (const float*)d_in[7];
    const float* Wv           = (const float*)d_in[8];
    const float* Wo           = (const float*)d_in[9];
    const float* attn_norm_w  = (const float*)d_in[10];
    const float* gate_W       = (const float*)d_in[11];
    const float* hidden_W     = (const float*)d_in[12];
    const float* ffn_out_W    = (const float*)d_in[13];
    const float* ffn_norm_w   = (const float*)d_in[14];
    const float* reward_norm_w= (const float*)d_in[15];
    const float* reward_W     = (const float*)d_in[16];
    const float* reward_b     = (const float*)d_in[17];
    const float* label_norm_w = (const float*)d_in[18];
    const float* label_W      = (const float*)d_in[19];
    const float* label_b      = (const float*)d_in[20];
    const float* box_norm_w   = (const float*)d_in[21];
    const float* boxh_W       = (const float*)d_in[22];
    const float* boxh_b       = (const float*)d_in[23];
    float* out = (float*)d_out;

    float *x, *hn, *qt, *kt, *vt, *q, *k, *sc, *gate, *hid;
    { void* p;
      cudaGetSymbolAddress(&p, g_x);    x    = (float*)p;
      cudaGetSymbolAddress(&p, g_hn);   hn   = (float*)p;
      cudaGetSymbolAddress(&p, g_qt);   qt   = (float*)p;
      cudaGetSymbolAddress(&p, g_kt);   kt   = (float*)p;
      cudaGetSymbolAddress(&p, g_vt);   vt   = (float*)p;
      cudaGetSymbolAddress(&p, g_q);    q    = (float*)p;
      cudaGetSymbolAddress(&p, g_k);    k    = (float*)p;
      cudaGetSymbolAddress(&p, g_sc);   sc   = (float*)p;
      cudaGetSymbolAddress(&p, g_gate); gate = (float*)p;
      cudaGetSymbolAddress(&p, g_hid);  hid  = (float*)p;
    }

    const dim3 m768 (D_MODEL/128, ROWS/128);   // (6, 32)
    const dim3 m3072(DFF/128,     ROWS/128);   // (24, 32)
    const dim3 m1000((1000+127)/128, ROWS/128);

    // ---- Embedding ----
    {
        int n = ROWS * 4 * 96;
        boxsin_kernel<<<(n + 255) / 256, 256>>>(box, gate);   // gate reused as box_sin
    }
    mma_gemm_kernel<false, true><<<m768, 256>>>(patch, patch_W, patch_b, x, ROWS, D_MODEL, D_MODEL);
    mma_gemm_kernel<true,  true><<<m768, 256>>>(gate,  box_W,   box_b,   x, ROWS, D_MODEL, D_MODEL);

    // ---- Layers ----
    for (int L = 0; L < NLAYERS; L++) {
        const float* wq  = Wq + (size_t)L * D_MODEL * D_MODEL;
        const float* wk  = Wk + (size_t)L * D_MODEL * D_MODEL;
        const float* wv  = Wv + (size_t)L * D_MODEL * D_MODEL;
        const float* wo  = Wo + (size_t)L * D_MODEL * D_MODEL;
        const float* anw = attn_norm_w + (size_t)L * D_MODEL;
        const float* gw  = gate_W   + (size_t)L * D_MODEL * DFF;
        const float* hw  = hidden_W + (size_t)L * D_MODEL * DFF;
        const float* ow  = ffn_out_W+ (size_t)L * DFF * D_MODEL;
        const float* fnw = ffn_norm_w + (size_t)L * D_MODEL;

        // attention
        rmsnorm_kernel<<<ROWS, 256>>>(x, anw, hn);
        mma_gemm_kernel<false, false><<<m768, 256>>>(hn, wq, nullptr, qt, ROWS, D_MODEL, D_MODEL);
        mma_gemm_kernel<false, false><<<m768, 256>>>(hn, wk, nullptr, kt, ROWS, D_MODEL, D_MODEL);
        mma_gemm_kernel<false, false><<<m768, 256>>>(hn, wv, nullptr, vt, ROWS, D_MODEL, D_MODEL);
        {
            int n = BATCH * SEQ * NH * 32;
            rope_kernel<<<(n + 255) / 256, 256>>>(qt, kt, q, k);
        }
        attn_scores_kernel<<<dim3(SEQ/64, SEQ/64, BATCH*NH), 256>>>(q, k, sc);
        softmax_kernel<<<BATCH*NH*SEQ, 128>>>(sc);
        attn_av_kernel<<<dim3(SEQ/64, BATCH*NH), 256>>>(sc, vt, qt);   // qt reused as O
        mma_gemm_kernel<true, false><<<m768, 256>>>(qt, wo, nullptr, x, ROWS, D_MODEL, D_MODEL);

        // FFN
        rmsnorm_kernel<<<ROWS, 256>>>(x, fnw, hn);
        mma_gemm_kernel<false, false><<<m3072, 256>>>(hn, gw, nullptr, gate, ROWS, DFF, D_MODEL);
        mma_gemm_kernel<false, false><<<m3072, 256>>>(hn, hw, nullptr, hid,  ROWS, DFF, D_MODEL);
        silu_mul_kernel<<<2048, 256>>>(gate, hid, ROWS * DFF);
        mma_gemm_kernel<true, false><<<m768, 256>>>(gate, ow, nullptr, x, ROWS, D_MODEL, DFF);
    }

    // ---- Heads ----
    float* out_reward = out;
    float* out_label  = out + (size_t)ROWS * 2;
    float* out_box    = out + (size_t)ROWS * 2 + (size_t)ROWS * 1000;

    rmsnorm_kernel<<<ROWS, 256>>>(x, reward_norm_w, hn);
    gemm_kernel<false, true><<<dim3(1, ROWS/64), 256>>>(hn, reward_W, reward_b, out_reward, ROWS, 2, D_MODEL);

    rmsnorm_kernel<<<ROWS, 256>>>(x, label_norm_w, hn);
    mma_gemm_kernel<false, true><<<m1000, 256>>>(hn, label_W, label_b, out_label, ROWS, 1000, D_MODEL);

    rmsnorm_kernel<<<ROWS, 256>>>(x, box_norm_w, hn);
    gemm_kernel<false, true><<<dim3(1, ROWS/64), 256>>>(hn, boxh_W, boxh_b, out_box, ROWS, 4, D_MODEL);
}